// round 15
// baseline (speedup 1.0000x reference)
#include <cuda_runtime.h>
#include <cuda_bf16.h>
#include <cstdint>

// Problem constants: N=512, B=256, F=400, D=14, K=2
#define GS_B 256
#define GS_F 400
#define GS_BF (GS_B * GS_F)      // 102400 images
#define GS_D 14
#define GS_DD (GS_D * GS_D)      // 196
#define GS_K 2

#define BFS 32                   // images per tile
#define NT (BFS * GS_D)          // 448 threads = 14 warps
#define NW (NT / 32)             // 14 warps
#define NTILES (GS_BF / BFS)     // 3200 tiles
#define GRIDP 592                // 148 SMs * 4 CTAs: exactly one wave
#define MAXT 6                   // max tiles per block
#define TILE_U4 (BFS * GS_DD / 4)  // 1568 uint4 per tile

typedef unsigned long long ull;

__device__ __forceinline__ float ex2f(float x) {
    float y;
    asm("ex2.approx.f32 %0, %1;" : "=f"(y) : "f"(x));
    return y;
}

#define PACK2(d, lo, hi) \
    asm("mov.b64 %0, {%1, %2};" : "=l"(d) : "f"(lo), "f"(hi))
#define MUL2(d, a, b) \
    asm("mul.rn.f32x2 %0, %1, %2;" : "=l"(d) : "l"(a), "l"(b))
#define ADD2(d, a, b) \
    asm("add.rn.f32x2 %0, %1, %2;" : "=l"(d) : "l"(a), "l"(b))

// Fully warp-autonomous persistent kernel: NO __syncthreads anywhere.
// Each warp digests all params for the <=4 images x 6 tiles it touches
// (private smem region), then free-runs its tile loop with warp-local
// sync only. Writeout = warp-local LDS + coalesced STG.128 (no TMA FIFO).
__global__ __launch_bounds__(NT, 4) void gs_warp(
    const int*          __restrict__ batch_idx,   // (B,)
    const unsigned int* __restrict__ m_mask,      // (B,F,K)
    const float*        __restrict__ height,      // (B,F,K)
    const float*        __restrict__ width,       // (B,F,K)
    const float*        __restrict__ x0,          // (B,F,K)
    const float*        __restrict__ y0,          // (B,F,K)
    const float*        __restrict__ background,  // (B,F)
    const float*        __restrict__ target_locs, // (N,F,2)
    float*              __restrict__ out)         // (B,F,D,D)
{
    // [warp][tile-slot][image-slot][4 x float4] : 14*6*4*4*16 = 21504 B
    __shared__ __align__(16) float4 sdig[NW][MAXT][4][4];
    __shared__ __align__(16) float  sbuf[NT * GS_D];      // 25088 B

    const int t    = threadIdx.x;
    const int wid  = t >> 5;
    const int lane = t & 31;
    const int bid  = blockIdx.x;

    const int wbase    = wid * 32;
    const int first_im = wbase / GS_D;     // first image slot this warp touches

    // ---- per-warp digest prologue: 48 digests over 2 lane-rounds ----
    for (int d = lane; d < MAXT * 4 * GS_K; d += 32) {
        const int tl   = d >> 3;               // tile slot 0..5
        const int tile = bid + tl * GRIDP;
        if (tile < NTILES) {
            const int r   = d & 7;
            const int im  = r >> 1;            // image slot 0..3
            const int k   = r & 1;
            const int iml = min(first_im + im, BFS - 1);
            const int bf  = tile * BFS + iml;
            const int b   = bf / GS_F;
            const int f   = bf - b * GS_F;

            const int   bi  = __ldg(&batch_idx[b]);
            const int   tlo = (bi * GS_F + f) * 2;
            const float tlx = __ldg(&target_locs[tlo]);
            const float tly = __ldg(&target_locs[tlo + 1]);

            const int i = bf * GS_K + k;
            const unsigned int m = __ldg(&m_mask[i]);
            const float h = (m != 0u) ? __ldg(&height[i]) : 0.0f;
            const float w = __ldg(&width[i]);
            const float invw2 = __fdividef(1.0f, w * w);

            const float HALF_LOG2E = 0.7213475204444817f;   // 0.5*log2(e)
            const float INV_2PI    = 0.15915494309189535f;

            const float aL  = -HALF_LOG2E * invw2;
            const float l2c = __log2f(h * INV_2PI * invw2); // h==0 -> -inf
            const float sx  = tlx + __ldg(&x0[i]);
            const float sy  = tly + __ldg(&y0[i]);

            const float base2 = fmaf(aL * sy, sy, l2c);
            const float v0 = ex2f(aL * (1.0f - 2.0f * sy));
            const float V  = ex2f(2.0f * aL);
            const float v1 = v0 * V;
            const float v2 = v1 * V;
            const float V2 = V * V;
            const float bgv = (k == 0) ? __ldg(&background[bf]) : 0.0f;

            sdig[wid][tl][im][2 * k]     = make_float4(sx, aL, base2, v0);
            sdig[wid][tl][im][2 * k + 1] = make_float4(v0 * v1, v1 * v2, V2 * V2, bgv);
        }
    }
    __syncwarp();    // warp-local: digests visible to the warp

    // ---- Phase B: free-running tile loop, warp-local only ----
    const int bfl = t / GS_D;             // image within tile
    const int px  = t - bfl * GS_D;       // row within image
    const float fpx = (float)px;
    const int imsl = bfl - first_im;      // image slot 0..3

    ull* sp = reinterpret_cast<ull*>(&sbuf[t * GS_D]);
    const uint4* sl = reinterpret_cast<const uint4*>(&sbuf[wbase * GS_D]);

#pragma unroll
    for (int tl = 0; tl < MAXT; ++tl) {
        const int tile = bid + tl * GRIDP;
        if (tile >= NTILES) break;

        const float4* pp = &sdig[wid][tl][imsl][0];
        const float4 p0 = pp[0];
        const float4 p1 = pp[1];
        const float4 p2 = pp[2];
        const float4 p3 = pp[3];

        ull A[7];
        ull bgp; PACK2(bgp, p1.w, p1.w);

        // spot 0
        {
            const float dx = fpx - p0.x;
            const float e0 = ex2f(fmaf(p0.y * dx, dx, p0.z));
            const float e1 = e0 * p0.w;
            ull E; PACK2(E, e0, e1);
            ull P; PACK2(P, p1.x, p1.y);
            ull Vp; PACK2(Vp, p1.z, p1.z);
#pragma unroll
            for (int j = 0; j < 7; ++j) {
                ADD2(A[j], bgp, E);
                if (j < 6) { MUL2(E, E, P); MUL2(P, P, Vp); }
            }
        }
        // spot 1
        {
            const float dx = fpx - p2.x;
            const float e0 = ex2f(fmaf(p2.y * dx, dx, p2.z));
            const float e1 = e0 * p2.w;
            ull E; PACK2(E, e0, e1);
            ull P; PACK2(P, p3.x, p3.y);
            ull Vp; PACK2(Vp, p3.z, p3.z);
#pragma unroll
            for (int j = 0; j < 7; ++j) {
                ADD2(A[j], A[j], E);
                if (j < 6) { MUL2(E, E, P); MUL2(P, P, Vp); }
            }
        }

        // warp-local staging
#pragma unroll
        for (int j = 0; j < 7; ++j) sp[j] = A[j];

        __syncwarp();

        // warp's 32 rows = contiguous 1792B span: coalesced STG.128
        uint4* og = reinterpret_cast<uint4*>(out)
                  + (size_t)tile * TILE_U4 + wid * 112;
        og[lane]      = sl[lane];
        og[lane + 32] = sl[lane + 32];
        og[lane + 64] = sl[lane + 64];
        if (lane < 16) og[lane + 96] = sl[lane + 96];

        __syncwarp();    // protect sbuf reuse next iteration
    }
}

extern "C" void kernel_launch(void* const* d_in, const int* in_sizes, int n_in,
                              void* d_out, int out_size) {
    const int*          batch_idx   = (const int*)d_in[0];
    const unsigned int* m_mask      = (const unsigned int*)d_in[1];
    const float*        height      = (const float*)d_in[2];
    const float*        width       = (const float*)d_in[3];
    const float*        x0          = (const float*)d_in[4];
    const float*        y0          = (const float*)d_in[5];
    const float*        background  = (const float*)d_in[6];
    const float*        target_locs = (const float*)d_in[7];
    // d_in[8] = pixel_pos: integer grid, regenerated analytically

    float* out = (float*)d_out;

    gs_warp<<<GRIDP, NT>>>(batch_idx, m_mask, height, width,
                           x0, y0, background, target_locs, out);
}

// round 16
// speedup vs baseline: 1.1009x; 1.1009x over previous
#include <cuda_runtime.h>
#include <cuda_bf16.h>
#include <cstdint>

// Problem constants: N=512, B=256, F=400, D=14, K=2
#define GS_B 256
#define GS_F 400
#define GS_BF (GS_B * GS_F)      // 102400 images
#define GS_D 14
#define GS_DD (GS_D * GS_D)      // 196
#define GS_K 2

#define BFS 32                   // images per tile
#define NT (BFS * GS_D)          // 448 threads = 14 warps
#define NTILES (GS_BF / BFS)     // 3200 tiles
#define GRIDP 592                // 148 SMs * 4 CTAs: one full wave
#define MAXT 6                   // max tiles per block
#define TILE_BYTES (BFS * GS_DD * 4)   // 25088 B per tile
#define WARP_BYTES 1792                // per-warp contiguous span

typedef unsigned long long ull;

__device__ __forceinline__ float ex2f(float x) {
    float y;
    asm("ex2.approx.f32 %0, %1;" : "=f"(y) : "f"(x));
    return y;
}

#define PACK2(d, lo, hi) \
    asm("mov.b64 %0, {%1, %2};" : "=l"(d) : "f"(lo), "f"(hi))
#define MUL2(d, a, b) \
    asm("mul.rn.f32x2 %0, %1, %2;" : "=l"(d) : "l"(a), "l"(b))
#define ADD2(d, a, b) \
    asm("add.rn.f32x2 %0, %1, %2;" : "=l"(d) : "l"(a), "l"(b))

__global__ __launch_bounds__(NT, 4) void gs_persist(
    const int*          __restrict__ batch_idx,   // (B,)
    const unsigned int* __restrict__ m_mask,      // (B,F,K)
    const float*        __restrict__ height,      // (B,F,K)
    const float*        __restrict__ width,       // (B,F,K)
    const float*        __restrict__ x0,          // (B,F,K)
    const float*        __restrict__ y0,          // (B,F,K)
    const float*        __restrict__ background,  // (B,F)
    const float*        __restrict__ target_locs, // (N,F,2)
    float*              __restrict__ out)         // (B,F,D,D)
{
    // slim digest: one float4 per (image,spot) + bg scalar
    __shared__ __align__(16) float4 sq[MAXT][BFS][GS_K];   // 6 KB
    __shared__ float                sbg[MAXT][BFS];        // 0.75 KB
    __shared__ __align__(16) float  sbuf[NT * GS_D];       // 24.5 KB

    const int t    = threadIdx.x;
    const int wid  = t >> 5;
    const int lane = t & 31;
    const int bid  = blockIdx.x;

    // ---- Phase A: up to 384 slim digests, one per thread ----
    if (t < MAXT * BFS * GS_K) {
        const int tl   = t >> 6;                 // tile slot 0..5
        const int tile = bid + tl * GRIDP;
        if (tile < NTILES) {
            const int r   = t & 63;
            const int iml = r >> 1;              // image within tile
            const int k   = r & 1;
            const int bf  = tile * BFS + iml;
            const int b   = bf / GS_F;
            const int f   = bf - b * GS_F;

            const int   bi  = __ldg(&batch_idx[b]);
            const int   tlo = (bi * GS_F + f) * 2;
            const float tlx = __ldg(&target_locs[tlo]);
            const float tly = __ldg(&target_locs[tlo + 1]);

            const int i = bf * GS_K + k;
            const unsigned int m = __ldg(&m_mask[i]);
            const float h = (m != 0u) ? __ldg(&height[i]) : 0.0f;
            const float w = __ldg(&width[i]);
            const float invw2 = __fdividef(1.0f, w * w);

            const float HALF_LOG2E = 0.7213475204444817f;   // 0.5*log2(e)
            const float INV_2PI    = 0.15915494309189535f;

            const float aL  = -HALF_LOG2E * invw2;
            const float l2c = __log2f(h * INV_2PI * invw2); // h==0 -> -inf
            const float sx  = tlx + __ldg(&x0[i]);
            const float sy  = tly + __ldg(&y0[i]);

            const float base2 = fmaf(aL * sy, sy, l2c);
            const float v0 = ex2f(aL * (1.0f - 2.0f * sy));

            sq[tl][iml][k] = make_float4(sx, aL, base2, v0);
            if (k == 0) sbg[tl][iml] = __ldg(&background[bf]);
        }
    }
    __syncthreads();     // the ONLY block barrier

    // ---- Phase B: free-running tile loop, per-warp TMA writeout ----
    const int bfl = t / GS_D;             // image within tile
    const int px  = t - bfl * GS_D;       // row within image
    const float fpx = (float)px;

    ull* sp = reinterpret_cast<ull*>(&sbuf[t * GS_D]);

    unsigned int ssrc;
    asm("{ .reg .u64 tmp; cvta.to.shared.u64 tmp, %1; cvt.u32.u64 %0, tmp; }"
        : "=r"(ssrc) : "l"(&sbuf[(wid * 32) * GS_D]));
    char* gdst = reinterpret_cast<char*>(out)
               + (size_t)bid * TILE_BYTES + wid * WARP_BYTES;
    const size_t gstep = (size_t)GRIDP * TILE_BYTES;

    bool first = true;

#pragma unroll
    for (int tl = 0; tl < MAXT; ++tl) {
        const int tile = bid + tl * GRIDP;
        if (tile >= NTILES) break;

        const float4 q0 = sq[tl][bfl][0];
        const float4 q1 = sq[tl][bfl][1];
        const float  bg = sbg[tl][bfl];

        ull A[7];
        ull bgp; PACK2(bgp, bg, bg);

        // spot 0: derive V,P0,P1,V4 from (aL, v0) in registers
        {
            const float V  = ex2f(2.0f * q0.y);
            const float V2 = V * V;
            const float P0 = q0.w * q0.w * V;
            const float P1 = P0 * V2;
            const float V4 = V2 * V2;
            const float dx = fpx - q0.x;
            const float e0 = ex2f(fmaf(q0.y * dx, dx, q0.z));
            const float e1 = e0 * q0.w;
            ull E; PACK2(E, e0, e1);
            ull P; PACK2(P, P0, P1);
            ull Vp; PACK2(Vp, V4, V4);
#pragma unroll
            for (int j = 0; j < 7; ++j) {
                ADD2(A[j], bgp, E);
                if (j < 6) { MUL2(E, E, P); MUL2(P, P, Vp); }
            }
        }
        // spot 1
        {
            const float V  = ex2f(2.0f * q1.y);
            const float V2 = V * V;
            const float P0 = q1.w * q1.w * V;
            const float P1 = P0 * V2;
            const float V4 = V2 * V2;
            const float dx = fpx - q1.x;
            const float e0 = ex2f(fmaf(q1.y * dx, dx, q1.z));
            const float e1 = e0 * q1.w;
            ull E; PACK2(E, e0, e1);
            ull P; PACK2(P, P0, P1);
            ull Vp; PACK2(Vp, V4, V4);
#pragma unroll
            for (int j = 0; j < 7; ++j) {
                ADD2(A[j], A[j], E);
                if (j < 6) { MUL2(E, E, P); MUL2(P, P, Vp); }
            }
        }

        // wait for TMA engine to finish READING sbuf from the previous tile
        if (!first && lane == 0)
            asm volatile("cp.async.bulk.wait_group.read 0;" ::: "memory");
        __syncwarp();

        // warp-local staging
#pragma unroll
        for (int j = 0; j < 7; ++j) sp[j] = A[j];

        __syncwarp();

        // one bulk async copy: warp's 1792B span, smem -> gmem
        if (lane == 0) {
            asm volatile("fence.proxy.async.shared::cta;" ::: "memory");
            asm volatile("cp.async.bulk.global.shared::cta.bulk_group [%0], [%1], %2;"
                         :: "l"(gdst), "r"(ssrc), "n"(WARP_BYTES) : "memory");
            asm volatile("cp.async.bulk.commit_group;" ::: "memory");
        }

        gdst += gstep;
        first = false;
    }

    // drain all bulk writes before exit
    if (lane == 0)
        asm volatile("cp.async.bulk.wait_group 0;" ::: "memory");
}

extern "C" void kernel_launch(void* const* d_in, const int* in_sizes, int n_in,
                              void* d_out, int out_size) {
    const int*          batch_idx   = (const int*)d_in[0];
    const unsigned int* m_mask      = (const unsigned int*)d_in[1];
    const float*        height      = (const float*)d_in[2];
    const float*        width       = (const float*)d_in[3];
    const float*        x0          = (const float*)d_in[4];
    const float*        y0          = (const float*)d_in[5];
    const float*        background  = (const float*)d_in[6];
    const float*        target_locs = (const float*)d_in[7];
    // d_in[8] = pixel_pos: integer grid, regenerated analytically

    float* out = (float*)d_out;

    gs_persist<<<GRIDP, NT>>>(batch_idx, m_mask, height, width,
                              x0, y0, background, target_locs, out);
}